// round 2
// baseline (speedup 1.0000x reference)
#include <cuda_runtime.h>
#include <math.h>

#define BDIM 4
#define TDIM 2048
#define CDIM 1024
#define HDIM 2048

#define BM 64
#define BN 64
#define BK 16

// Scratch (device globals: allocation-free rule)
__device__ float g_q[(size_t)BDIM * TDIM * HDIM];
__device__ float g_k[(size_t)BDIM * TDIM * HDIM];
__device__ float g_v[(size_t)BDIM * TDIM * HDIM];
__device__ float g_s[(size_t)BDIM * TDIM * TDIM];

// C[m,n] = alpha * sum_k A[m*K+k] * B[n*K+k]   (both operands K-major, "NT")
// Per-z batch strides. If causal, skip tiles entirely above the diagonal.
__global__ __launch_bounds__(256) void gemm_nt(
    const float* __restrict__ A, const float* __restrict__ B, float* __restrict__ C,
    int M, int N, int K,
    long strideA, long strideB, long strideC,
    float alpha, int causal)
{
    const int b = blockIdx.z;
    A += (long)b * strideA;
    B += (long)b * strideB;
    C += (long)b * strideC;

    const int m0 = blockIdx.y * BM;
    const int n0 = blockIdx.x * BN;
    if (causal && n0 > m0 + BM - 1) return;  // tile fully masked

    __shared__ float As[BK][BM];
    __shared__ float Bs[BK][BN];

    const int tid = threadIdx.x;
    const int tx = tid & 15;        // 0..15 -> n
    const int ty = tid >> 4;        // 0..15 -> m

    float acc[4][4] = {};

    for (int k0 = 0; k0 < K; k0 += BK) {
        // Load 64x16 A tile (k fastest within a row -> coalesced 64B chunks)
        #pragma unroll
        for (int i = 0; i < 4; i++) {
            int idx = tid + i * 256;
            int r  = idx >> 4;
            int kk = idx & 15;
            As[kk][r] = A[(long)(m0 + r) * K + k0 + kk];
        }
        #pragma unroll
        for (int i = 0; i < 4; i++) {
            int idx = tid + i * 256;
            int r  = idx >> 4;
            int kk = idx & 15;
            Bs[kk][r] = B[(long)(n0 + r) * K + k0 + kk];
        }
        __syncthreads();

        #pragma unroll
        for (int kk = 0; kk < BK; kk++) {
            float4 a = *(const float4*)&As[kk][ty * 4];
            float4 bv = *(const float4*)&Bs[kk][tx * 4];
            float av[4] = {a.x, a.y, a.z, a.w};
            float bb[4] = {bv.x, bv.y, bv.z, bv.w};
            #pragma unroll
            for (int i = 0; i < 4; i++)
                #pragma unroll
                for (int j = 0; j < 4; j++)
                    acc[i][j] += av[i] * bb[j];
        }
        __syncthreads();
    }

    #pragma unroll
    for (int i = 0; i < 4; i++) {
        long row = (long)(m0 + ty * 4 + i) * N + n0 + tx * 4;
        float4 o;
        o.x = alpha * acc[i][0];
        o.y = alpha * acc[i][1];
        o.z = alpha * acc[i][2];
        o.w = alpha * acc[i][3];
        *(float4*)&C[row] = o;
    }
}

// O[t,h] = sum_s P[t*T+s] * V[s*H+h]   ("NN"), k-loop clamped by causality.
__global__ __launch_bounds__(256) void gemm_nn_pv(
    const float* __restrict__ P, const float* __restrict__ V, float* __restrict__ O)
{
    const int b = blockIdx.z;
    P += (long)b * TDIM * TDIM;
    V += (long)b * TDIM * HDIM;
    O += (long)b * TDIM * HDIM;

    const int m0 = blockIdx.y * BM;   // t
    const int n0 = blockIdx.x * BN;   // h
    const int kmax = m0 + BM;         // s < kmax (multiple of BK); rest is zero in P

    __shared__ float As[BK][BM];
    __shared__ float Bs[BK][BN];

    const int tid = threadIdx.x;
    const int tx = tid & 15;
    const int ty = tid >> 4;

    float acc[4][4] = {};

    for (int k0 = 0; k0 < kmax; k0 += BK) {
        #pragma unroll
        for (int i = 0; i < 4; i++) {
            int idx = tid + i * 256;
            int r  = idx >> 4;
            int kk = idx & 15;
            As[kk][r] = P[(long)(m0 + r) * TDIM + k0 + kk];
        }
        // V tile: Bs[kk][n], n contiguous -> fully coalesced
        #pragma unroll
        for (int i = 0; i < 4; i++) {
            int idx = tid + i * 256;
            int kk = idx >> 6;
            int n  = idx & 63;
            Bs[kk][n] = V[(long)(k0 + kk) * HDIM + n0 + n];
        }
        __syncthreads();

        #pragma unroll
        for (int kk = 0; kk < BK; kk++) {
            float4 a = *(const float4*)&As[kk][ty * 4];
            float4 bv = *(const float4*)&Bs[kk][tx * 4];
            float av[4] = {a.x, a.y, a.z, a.w};
            float bb[4] = {bv.x, bv.y, bv.z, bv.w};
            #pragma unroll
            for (int i = 0; i < 4; i++)
                #pragma unroll
                for (int j = 0; j < 4; j++)
                    acc[i][j] += av[i] * bb[j];
        }
        __syncthreads();
    }

    #pragma unroll
    for (int i = 0; i < 4; i++) {
        long row = (long)(m0 + ty * 4 + i) * HDIM + n0 + tx * 4;
        float4 o = {acc[i][0], acc[i][1], acc[i][2], acc[i][3]};
        *(float4*)&O[row] = o;
    }
}

// Causal row softmax in place. Row t: valid cols [0, t]; cols (t, T) set to 0.
__global__ __launch_bounds__(256) void softmax_causal(float* __restrict__ S)
{
    const int t = blockIdx.x;
    const int b = blockIdx.y;
    float* row = S + ((long)b * TDIM + t) * TDIM;
    const int n = t + 1;
    const int tid = threadIdx.x;

    __shared__ float red[256];

    // max
    float mx = -INFINITY;
    for (int i = tid; i < n; i += 256) mx = fmaxf(mx, row[i]);
    red[tid] = mx;
    __syncthreads();
    for (int s = 128; s > 0; s >>= 1) {
        if (tid < s) red[tid] = fmaxf(red[tid], red[tid + s]);
        __syncthreads();
    }
    mx = red[0];
    __syncthreads();

    // exp + sum
    float sum = 0.f;
    for (int i = tid; i < n; i += 256) {
        float e = expf(row[i] - mx);
        row[i] = e;
        sum += e;
    }
    red[tid] = sum;
    __syncthreads();
    for (int s = 128; s > 0; s >>= 1) {
        if (tid < s) red[tid] += red[tid + s];
        __syncthreads();
    }
    const float inv = 1.0f / red[0];
    __syncthreads();

    for (int i = tid; i < n; i += 256) row[i] *= inv;
    // zero the masked tail so PV GEMM needs no masking
    for (int i = n + tid; i < TDIM; i += 256) row[i] = 0.f;
}

extern "C" void kernel_launch(void* const* d_in, const int* in_sizes, int n_in,
                              void* d_out, int out_size)
{
    const float* x  = (const float*)d_in[0];
    const float* Wk = (const float*)d_in[1];
    const float* Wq = (const float*)d_in[2];
    const float* Wv = (const float*)d_in[3];
    float* out = (float*)d_out;

    float *q, *k, *v, *s;
    cudaGetSymbolAddress((void**)&q, g_q);
    cudaGetSymbolAddress((void**)&k, g_k);
    cudaGetSymbolAddress((void**)&v, g_v);
    cudaGetSymbolAddress((void**)&s, g_s);

    const int M = BDIM * TDIM;  // 8192 rows for projections

    // Projections: [8192,1024] @ [2048,1024]^T -> [8192,2048]
    {
        dim3 grid(HDIM / BN, M / BM, 1);
        gemm_nt<<<grid, 256>>>(x, Wq, q, M, HDIM, CDIM, 0, 0, 0, 1.0f, 0);
        gemm_nt<<<grid, 256>>>(x, Wk, k, M, HDIM, CDIM, 0, 0, 0, 1.0f, 0);
        gemm_nt<<<grid, 256>>>(x, Wv, v, M, HDIM, CDIM, 0, 0, 0, 1.0f, 0);
    }

    // S = scale * Q @ K^T  (causal tiles only), batched over B
    {
        const float scale = 1.0f / sqrtf((float)HDIM);
        dim3 grid(TDIM / BN, TDIM / BM, BDIM);
        gemm_nt<<<grid, 256>>>(q, k, s, TDIM, TDIM, HDIM,
                               (long)TDIM * HDIM, (long)TDIM * HDIM,
                               (long)TDIM * TDIM, scale, 1);
    }

    // causal softmax in place
    {
        dim3 grid(TDIM, BDIM);
        softmax_causal<<<grid, 256>>>(s);
    }

    // O = P @ V
    {
        dim3 grid(HDIM / BN, TDIM / BM, BDIM);
        gemm_nn_pv<<<grid, 256>>>(s, v, out);
    }
}

// round 7
// speedup vs baseline: 4.3062x; 4.3062x over previous
#include <cuda_runtime.h>
#include <cuda_bf16.h>
#include <cstdint>
#include <math.h>

#define BDIM 4
#define TDIM 2048
#define CDIM 1024
#define HDIM 2048

#define BM 128
#define BN 128
#define BK 32
#define SPADH 40   // bf16 elements per smem row (stride) -> conflict-free frags

// Scratch (device globals: allocation-free rule)
__device__ float g_q[(size_t)BDIM * TDIM * HDIM];
__device__ float g_k[(size_t)BDIM * TDIM * HDIM];
__device__ float g_v[(size_t)BDIM * TDIM * HDIM];
__device__ float g_vt[(size_t)BDIM * TDIM * HDIM];
__device__ float g_s[(size_t)BDIM * TDIM * TDIM];

// m16n8k16 bf16 MMA (sm_80+ baseline PTX)
__device__ __forceinline__ void mma_bf16(float* c, const uint32_t* a, const uint32_t* b) {
    asm volatile(
        "mma.sync.aligned.m16n8k16.row.col.f32.bf16.bf16.f32 "
        "{%0,%1,%2,%3}, {%4,%5,%6,%7}, {%8,%9}, {%0,%1,%2,%3};"
        : "+f"(c[0]), "+f"(c[1]), "+f"(c[2]), "+f"(c[3])
        : "r"(a[0]), "r"(a[1]), "r"(a[2]), "r"(a[3]), "r"(b[0]), "r"(b[1]));
}

// ---------------- 3xBF16 NT GEMM ----------------
// C[m,n] = sum_k A[m*K+k] * B[n*K+k]; CTA tile 128x128, K staged by 32.
// causal: skip tiles with n0 > m0.  clampk: k-loop only to m0+BM (P zero beyond).
__global__ __launch_bounds__(256, 2) void mma_nt(
    const float* __restrict__ A, const float* __restrict__ B, float* __restrict__ C,
    int K, int ldc, long sA, long sB, long sC, int causal, int clampk)
{
    const int m0 = blockIdx.y * BM;
    const int n0 = blockIdx.x * BN;
    if (causal && n0 > m0) return;

    const int b = blockIdx.z;
    A += (long)b * sA;  B += (long)b * sB;  C += (long)b * sC;

    __shared__ __nv_bfloat16 Ah[BM][SPADH];
    __shared__ __nv_bfloat16 Al[BM][SPADH];
    __shared__ __nv_bfloat16 Bh[BN][SPADH];
    __shared__ __nv_bfloat16 Bl[BN][SPADH];

    const int tid  = threadIdx.x;
    const int wid  = tid >> 5;
    const int lane = tid & 31;
    const int g  = lane >> 2;        // group id 0..7
    const int tg = lane & 3;         // thread-in-group 0..3
    const int wm = (wid >> 2) * 64;  // warp row base (0 / 64)
    const int wn = (wid & 3) * 32;   // warp col base (0/32/64/96)

    float acc[4][4][4] = {};         // [mt][nt][4]

    const int kEnd = clampk ? (m0 + BM) : K;

    for (int k0 = 0; k0 < kEnd; k0 += BK) {
        // Stage 128x32 hi/lo bf16 tiles of A and B
        #pragma unroll
        for (int i = 0; i < 4; i++) {
            int idx = tid + i * 256;
            int r = idx >> 3, c4 = idx & 7;
            {
                float4 va = *(const float4*)(A + (long)(m0 + r) * K + k0 + c4 * 4);
                __nv_bfloat162 h01 = __float22bfloat162_rn(make_float2(va.x, va.y));
                __nv_bfloat162 h23 = __float22bfloat162_rn(make_float2(va.z, va.w));
                __nv_bfloat162 l01 = __float22bfloat162_rn(make_float2(
                    va.x - __bfloat162float(h01.x), va.y - __bfloat162float(h01.y)));
                __nv_bfloat162 l23 = __float22bfloat162_rn(make_float2(
                    va.z - __bfloat162float(h23.x), va.w - __bfloat162float(h23.y)));
                *(__nv_bfloat162*)&Ah[r][c4 * 4]     = h01;
                *(__nv_bfloat162*)&Ah[r][c4 * 4 + 2] = h23;
                *(__nv_bfloat162*)&Al[r][c4 * 4]     = l01;
                *(__nv_bfloat162*)&Al[r][c4 * 4 + 2] = l23;
            }
            {
                float4 vb = *(const float4*)(B + (long)(n0 + r) * K + k0 + c4 * 4);
                __nv_bfloat162 h01 = __float22bfloat162_rn(make_float2(vb.x, vb.y));
                __nv_bfloat162 h23 = __float22bfloat162_rn(make_float2(vb.z, vb.w));
                __nv_bfloat162 l01 = __float22bfloat162_rn(make_float2(
                    vb.x - __bfloat162float(h01.x), vb.y - __bfloat162float(h01.y)));
                __nv_bfloat162 l23 = __float22bfloat162_rn(make_float2(
                    vb.z - __bfloat162float(h23.x), vb.w - __bfloat162float(h23.y)));
                *(__nv_bfloat162*)&Bh[r][c4 * 4]     = h01;
                *(__nv_bfloat162*)&Bh[r][c4 * 4 + 2] = h23;
                *(__nv_bfloat162*)&Bl[r][c4 * 4]     = l01;
                *(__nv_bfloat162*)&Bl[r][c4 * 4 + 2] = l23;
            }
        }
        __syncthreads();

        #pragma unroll
        for (int ks = 0; ks < BK; ks += 16) {
            // Phase 1: ah * bh
            uint32_t af[4][4], bf[4][2];
            #pragma unroll
            for (int mt = 0; mt < 4; mt++) {
                const __nv_bfloat16* ap = &Ah[wm + mt * 16 + g][ks + 2 * tg];
                af[mt][0] = *(const uint32_t*)(ap);
                af[mt][1] = *(const uint32_t*)(ap + 8 * SPADH);
                af[mt][2] = *(const uint32_t*)(ap + 8);
                af[mt][3] = *(const uint32_t*)(ap + 8 * SPADH + 8);
            }
            #pragma unroll
            for (int nt = 0; nt < 4; nt++) {
                const __nv_bfloat16* bp = &Bh[wn + nt * 8 + g][ks + 2 * tg];
                bf[nt][0] = *(const uint32_t*)(bp);
                bf[nt][1] = *(const uint32_t*)(bp + 8);
            }
            #pragma unroll
            for (int mt = 0; mt < 4; mt++)
                #pragma unroll
                for (int nt = 0; nt < 4; nt++)
                    mma_bf16(acc[mt][nt], af[mt], bf[nt]);

            // Phase 2: ah * bl  (reuse af, new b frags)
            uint32_t bl[4][2];
            #pragma unroll
            for (int nt = 0; nt < 4; nt++) {
                const __nv_bfloat16* bp = &Bl[wn + nt * 8 + g][ks + 2 * tg];
                bl[nt][0] = *(const uint32_t*)(bp);
                bl[nt][1] = *(const uint32_t*)(bp + 8);
            }
            #pragma unroll
            for (int mt = 0; mt < 4; mt++)
                #pragma unroll
                for (int nt = 0; nt < 4; nt++)
                    mma_bf16(acc[mt][nt], af[mt], bl[nt]);

            // Phase 3: al * bh  (overwrite af with lo, reuse bf)
            #pragma unroll
            for (int mt = 0; mt < 4; mt++) {
                const __nv_bfloat16* ap = &Al[wm + mt * 16 + g][ks + 2 * tg];
                af[mt][0] = *(const uint32_t*)(ap);
                af[mt][1] = *(const uint32_t*)(ap + 8 * SPADH);
                af[mt][2] = *(const uint32_t*)(ap + 8);
                af[mt][3] = *(const uint32_t*)(ap + 8 * SPADH + 8);
            }
            #pragma unroll
            for (int mt = 0; mt < 4; mt++)
                #pragma unroll
                for (int nt = 0; nt < 4; nt++)
                    mma_bf16(acc[mt][nt], af[mt], bf[nt]);
        }
        __syncthreads();
    }

    // Epilogue: direct stores (float2 per row-pair)
    #pragma unroll
    for (int mt = 0; mt < 4; mt++) {
        #pragma unroll
        for (int nt = 0; nt < 4; nt++) {
            const int row = m0 + wm + mt * 16 + g;
            const int col = n0 + wn + nt * 8 + tg * 2;
            float2 lo = {acc[mt][nt][0], acc[mt][nt][1]};
            float2 hi = {acc[mt][nt][2], acc[mt][nt][3]};
            *(float2*)&C[(long)row * ldc + col] = lo;
            *(float2*)&C[(long)(row + 8) * ldc + col] = hi;
        }
    }
}

// ---------------- causal softmax (scale folded), zero tail to next 128 ----------------
__global__ __launch_bounds__(256) void softmax_causal(float* __restrict__ S, float scale)
{
    const int t = blockIdx.x;
    const int b = blockIdx.y;
    float* row = S + ((long)b * TDIM + t) * TDIM;
    const int n = t + 1;
    const int nend = ((t >> 7) + 1) << 7;   // next multiple of 128 (covers diag tile)
    const int tid = threadIdx.x;

    __shared__ float red[256];

    float mx = -INFINITY;
    for (int i = tid; i < n; i += 256) mx = fmaxf(mx, row[i] * scale);
    red[tid] = mx;
    __syncthreads();
    for (int s = 128; s > 0; s >>= 1) {
        if (tid < s) red[tid] = fmaxf(red[tid], red[tid + s]);
        __syncthreads();
    }
    mx = red[0];
    __syncthreads();

    float sum = 0.f;
    for (int i = tid; i < n; i += 256) {
        float e = __expf(row[i] * scale - mx);
        row[i] = e;
        sum += e;
    }
    red[tid] = sum;
    __syncthreads();
    for (int s = 128; s > 0; s >>= 1) {
        if (tid < s) red[tid] += red[tid + s];
        __syncthreads();
    }
    const float inv = 1.0f / red[0];
    __syncthreads();

    for (int i = tid; i < n; i += 256) row[i] *= inv;
    for (int i = n + tid; i < nend; i += 256) row[i] = 0.f;  // mask tail in diag tile
}

// ---------------- batched transpose: vt[b][h][t] = v[b][t][h] ----------------
__global__ __launch_bounds__(256) void transpose_bth(
    const float* __restrict__ V, float* __restrict__ VT)
{
    __shared__ float ts[32][33];
    const int b = blockIdx.z;
    const int t0 = blockIdx.x * 32;
    const int h0 = blockIdx.y * 32;
    const int tx = threadIdx.x, ty = threadIdx.y;   // 32 x 8

    const float* v = V + (long)b * TDIM * HDIM;
    float* vt = VT + (long)b * TDIM * HDIM;

    #pragma unroll
    for (int i = 0; i < 4; i++)
        ts[ty + 8 * i][tx] = v[(long)(t0 + ty + 8 * i) * HDIM + h0 + tx];
    __syncthreads();
    #pragma unroll
    for (int i = 0; i < 4; i++)
        vt[(long)(h0 + ty + 8 * i) * TDIM + t0 + tx] = ts[tx][ty + 8 * i];
}

// ---------------- driver ----------------
extern "C" void kernel_launch(void* const* d_in, const int* in_sizes, int n_in,
                              void* d_out, int out_size)
{
    const float* x  = (const float*)d_in[0];
    const float* Wk = (const float*)d_in[1];
    const float* Wq = (const float*)d_in[2];
    const float* Wv = (const float*)d_in[3];
    float* out = (float*)d_out;

    float *q, *k, *v, *vt, *s;
    cudaGetSymbolAddress((void**)&q,  g_q);
    cudaGetSymbolAddress((void**)&k,  g_k);
    cudaGetSymbolAddress((void**)&v,  g_v);
    cudaGetSymbolAddress((void**)&vt, g_vt);
    cudaGetSymbolAddress((void**)&s,  g_s);

    const int M = BDIM * TDIM;   // 8192

    // Projections: [8192,1024] @ [2048,1024]^T
    {
        dim3 grid(HDIM / BN, M / BM, 1);
        mma_nt<<<grid, 256>>>(x, Wq, q, CDIM, HDIM, 0, 0, 0, 0, 0);
        mma_nt<<<grid, 256>>>(x, Wk, k, CDIM, HDIM, 0, 0, 0, 0, 0);
        mma_nt<<<grid, 256>>>(x, Wv, v, CDIM, HDIM, 0, 0, 0, 0, 0);
    }

    // S = Q @ K^T (causal tiles only), batched
    {
        dim3 grid(TDIM / BN, TDIM / BM, BDIM);
        mma_nt<<<grid, 256>>>(q, k, s, HDIM, TDIM,
                              (long)TDIM * HDIM, (long)TDIM * HDIM, (long)TDIM * TDIM,
                              1, 0);
    }

    // softmax (scale folded)
    {
        dim3 grid(TDIM, BDIM);
        softmax_causal<<<grid, 256>>>(s, 1.0f / sqrtf((float)HDIM));
    }

    // V^T for NT-form PV gemm
    {
        dim3 grid(TDIM / 32, HDIM / 32, BDIM);
        transpose_bth<<<grid, dim3(32, 8)>>>(v, vt);
    }

    // O = P @ V  ==  P[T,T] x Vt[H,T]^T, k-loop clamped to diagonal
    {
        dim3 grid(HDIM / BN, TDIM / BM, BDIM);
        mma_nt<<<grid, 256>>>(s, vt, out, TDIM, HDIM,
                              (long)TDIM * TDIM, (long)TDIM * HDIM, (long)TDIM * HDIM,
                              0, 1);
    }
}

// round 10
// speedup vs baseline: 4.8139x; 1.1179x over previous
#include <cuda_runtime.h>
#include <cuda_bf16.h>
#include <cstdint>
#include <math.h>

#define BDIM 4
#define TDIM 2048
#define CDIM 1024
#define HDIM 2048

#define BM 128
#define BN 128
#define BK 32
#define SPADH 40                 // bf16 per smem row (80B: 16B-aligned, conflict-free)
#define TILE_E (BM * SPADH)      // bf16 elems per tile buffer
#define SMEM_BYTES (2 * 4 * TILE_E * 2)   // 2 stages x 4 tiles x 10240B = 81920

// ---- global scratch planes (allocation-free rule) ----
#define NXC ((size_t)BDIM * TDIM * CDIM)
#define NWH ((size_t)HDIM * CDIM)
#define NTH ((size_t)BDIM * TDIM * HDIM)
#define NTT ((size_t)BDIM * TDIM * TDIM)
__device__ __nv_bfloat16 g_xh[NXC], g_xl[NXC];
__device__ __nv_bfloat16 g_wh[3][NWH], g_wl[3][NWH];
__device__ __nv_bfloat16 g_qh[NTH], g_ql[NTH], g_kh[NTH], g_kl[NTH];
__device__ __nv_bfloat16 g_vh[NTH], g_vl[NTH], g_vth[NTH], g_vtl[NTH];
__device__ float g_s[NTT];
__device__ __nv_bfloat16 g_ph[NTT], g_pl[NTT];

// m16n8k16 bf16 MMA (sm_80+ baseline PTX)
__device__ __forceinline__ void mma_bf16(float* c, const uint32_t* a, const uint32_t* b) {
    asm volatile(
        "mma.sync.aligned.m16n8k16.row.col.f32.bf16.bf16.f32 "
        "{%0,%1,%2,%3}, {%4,%5,%6,%7}, {%8,%9}, {%0,%1,%2,%3};"
        : "+f"(c[0]), "+f"(c[1]), "+f"(c[2]), "+f"(c[3])
        : "r"(a[0]), "r"(a[1]), "r"(a[2]), "r"(a[3]), "r"(b[0]), "r"(b[1]));
}

#define CP_COMMIT() asm volatile("cp.async.commit_group;" ::: "memory")
#define CP_WAIT0()  asm volatile("cp.async.wait_group 0;" ::: "memory")
#define CP_WAIT1()  asm volatile("cp.async.wait_group 1;" ::: "memory")

// ---------------- 3xBF16 NT GEMM, cp.async double-buffered ----------------
// C[m,n] = sum_k A[m*K+k]*B[n*K+k], A/B given as hi/lo bf16 planes (K-major).
// split=0: write f32 to Cf.  split=1: write hi/lo bf16 planes Ch/Cl.
__global__ __launch_bounds__(256, 2) void mma_nt(
    const __nv_bfloat16* __restrict__ Ah, const __nv_bfloat16* __restrict__ Al,
    const __nv_bfloat16* __restrict__ Bh, const __nv_bfloat16* __restrict__ Bl,
    float* __restrict__ Cf, __nv_bfloat16* __restrict__ Ch, __nv_bfloat16* __restrict__ Cl,
    int K, int ldc, long sA, long sB, long sC, int causal, int clampk, int split)
{
    const int m0 = blockIdx.y * BM;
    const int n0 = blockIdx.x * BN;
    if (causal && n0 > m0) return;

    const int b = blockIdx.z;
    Ah += (long)b * sA;  Al += (long)b * sA;
    Bh += (long)b * sB;  Bl += (long)b * sB;

    extern __shared__ __nv_bfloat16 sm[];

    const int tid  = threadIdx.x;
    const int wid  = tid >> 5;
    const int lane = tid & 31;
    const int g  = lane >> 2;
    const int tg = lane & 3;
    const int wm = (wid >> 2) * 64;
    const int wn = (wid & 3) * 32;

    const int kEnd = clampk ? (m0 + BM) : K;
    const int nstages = kEnd / BK;

    // chunk coords for this thread (2 chunks of 16B per tile per thread)
    const int r0c = tid >> 2,          c0c = tid & 3;
    const int r1c = (tid + 256) >> 2,  c1c = (tid + 256) & 3;

    const __nv_bfloat16* planes[4] = {Ah, Al, Bh, Bl};
    const int rbase[4] = {m0, m0, n0, n0};

    // stage loader: buf in {0,1}
    auto load_stage = [&](int buf, int k0) {
        #pragma unroll
        for (int p = 0; p < 4; p++) {
            __nv_bfloat16* tb = sm + (buf * 4 + p) * TILE_E;
            {
                uint32_t dst = (uint32_t)__cvta_generic_to_shared(tb + r0c * SPADH + c0c * 8);
                const void* src = planes[p] + (long)(rbase[p] + r0c) * K + k0 + c0c * 8;
                asm volatile("cp.async.cg.shared.global [%0], [%1], 16;" :: "r"(dst), "l"(src));
            }
            {
                uint32_t dst = (uint32_t)__cvta_generic_to_shared(tb + r1c * SPADH + c1c * 8);
                const void* src = planes[p] + (long)(rbase[p] + r1c) * K + k0 + c1c * 8;
                asm volatile("cp.async.cg.shared.global [%0], [%1], 16;" :: "r"(dst), "l"(src));
            }
        }
        CP_COMMIT();
    };

    float acc[4][4][4] = {};

    load_stage(0, 0);

    for (int s = 0; s < nstages; s++) {
        if (s + 1 < nstages) { load_stage((s + 1) & 1, (s + 1) * BK); CP_WAIT1(); }
        else                 { CP_WAIT0(); }
        __syncthreads();

        const __nv_bfloat16* smAh = sm + ((s & 1) * 4 + 0) * TILE_E;
        const __nv_bfloat16* smAl = sm + ((s & 1) * 4 + 1) * TILE_E;
        const __nv_bfloat16* smBh = sm + ((s & 1) * 4 + 2) * TILE_E;
        const __nv_bfloat16* smBl = sm + ((s & 1) * 4 + 3) * TILE_E;

        #pragma unroll
        for (int ks = 0; ks < BK; ks += 16) {
            uint32_t af[4][4], bf[4][2];
            // Phase 1: ah * bh
            #pragma unroll
            for (int mt = 0; mt < 4; mt++) {
                const __nv_bfloat16* ap = smAh + (wm + mt * 16 + g) * SPADH + ks + 2 * tg;
                af[mt][0] = *(const uint32_t*)(ap);
                af[mt][1] = *(const uint32_t*)(ap + 8 * SPADH);
                af[mt][2] = *(const uint32_t*)(ap + 8);
                af[mt][3] = *(const uint32_t*)(ap + 8 * SPADH + 8);
            }
            #pragma unroll
            for (int nt = 0; nt < 4; nt++) {
                const __nv_bfloat16* bp = smBh + (wn + nt * 8 + g) * SPADH + ks + 2 * tg;
                bf[nt][0] = *(const uint32_t*)(bp);
                bf[nt][1] = *(const uint32_t*)(bp + 8);
            }
            #pragma unroll
            for (int mt = 0; mt < 4; mt++)
                #pragma unroll
                for (int nt = 0; nt < 4; nt++)
                    mma_bf16(acc[mt][nt], af[mt], bf[nt]);

            // Phase 2: ah * bl
            uint32_t bl[4][2];
            #pragma unroll
            for (int nt = 0; nt < 4; nt++) {
                const __nv_bfloat16* bp = smBl + (wn + nt * 8 + g) * SPADH + ks + 2 * tg;
                bl[nt][0] = *(const uint32_t*)(bp);
                bl[nt][1] = *(const uint32_t*)(bp + 8);
            }
            #pragma unroll
            for (int mt = 0; mt < 4; mt++)
                #pragma unroll
                for (int nt = 0; nt < 4; nt++)
                    mma_bf16(acc[mt][nt], af[mt], bl[nt]);

            // Phase 3: al * bh
            #pragma unroll
            for (int mt = 0; mt < 4; mt++) {
                const __nv_bfloat16* ap = smAl + (wm + mt * 16 + g) * SPADH + ks + 2 * tg;
                af[mt][0] = *(const uint32_t*)(ap);
                af[mt][1] = *(const uint32_t*)(ap + 8 * SPADH);
                af[mt][2] = *(const uint32_t*)(ap + 8);
                af[mt][3] = *(const uint32_t*)(ap + 8 * SPADH + 8);
            }
            #pragma unroll
            for (int mt = 0; mt < 4; mt++)
                #pragma unroll
                for (int nt = 0; nt < 4; nt++)
                    mma_bf16(acc[mt][nt], af[mt], bf[nt]);
        }
        __syncthreads();
    }

    // ---- epilogue ----
    if (split) {
        Ch += (long)blockIdx.z * sC;  Cl += (long)blockIdx.z * sC;
        #pragma unroll
        for (int mt = 0; mt < 4; mt++) {
            #pragma unroll
            for (int nt = 0; nt < 4; nt++) {
                const int row = m0 + wm + mt * 16 + g;
                const int col = n0 + wn + nt * 8 + tg * 2;
                #pragma unroll
                for (int h = 0; h < 2; h++) {
                    float2 v = {acc[mt][nt][2 * h], acc[mt][nt][2 * h + 1]};
                    __nv_bfloat162 hp = __float22bfloat162_rn(v);
                    __nv_bfloat162 lp = __float22bfloat162_rn(make_float2(
                        v.x - __bfloat162float(hp.x), v.y - __bfloat162float(hp.y)));
                    long off = (long)(row + 8 * h) * ldc + col;
                    *(__nv_bfloat162*)&Ch[off] = hp;
                    *(__nv_bfloat162*)&Cl[off] = lp;
                }
            }
        }
    } else {
        Cf += (long)blockIdx.z * sC;
        #pragma unroll
        for (int mt = 0; mt < 4; mt++) {
            #pragma unroll
            for (int nt = 0; nt < 4; nt++) {
                const int row = m0 + wm + mt * 16 + g;
                const int col = n0 + wn + nt * 8 + tg * 2;
                float2 lo = {acc[mt][nt][0], acc[mt][nt][1]};
                float2 hi = {acc[mt][nt][2], acc[mt][nt][3]};
                *(float2*)&Cf[(long)row * ldc + col] = lo;
                *(float2*)&Cf[(long)(row + 8) * ldc + col] = hi;
            }
        }
    }
}

// ---------------- f32 -> hi/lo bf16 planes ----------------
__global__ __launch_bounds__(256) void split_f32(
    const float* __restrict__ src, __nv_bfloat16* __restrict__ h,
    __nv_bfloat16* __restrict__ l, long n4)
{
    long i = ((long)blockIdx.x * 256 + threadIdx.x);
    if (i >= n4) return;
    float4 v = *(const float4*)(src + i * 4);
    __nv_bfloat162 h01 = __float22bfloat162_rn(make_float2(v.x, v.y));
    __nv_bfloat162 h23 = __float22bfloat162_rn(make_float2(v.z, v.w));
    __nv_bfloat162 l01 = __float22bfloat162_rn(make_float2(
        v.x - __bfloat162float(h01.x), v.y - __bfloat162float(h01.y)));
    __nv_bfloat162 l23 = __float22bfloat162_rn(make_float2(
        v.z - __bfloat162float(h23.x), v.w - __bfloat162float(h23.y)));
    *(__nv_bfloat162*)&h[i * 4]     = h01;
    *(__nv_bfloat162*)&h[i * 4 + 2] = h23;
    *(__nv_bfloat162*)&l[i * 4]     = l01;
    *(__nv_bfloat162*)&l[i * 4 + 2] = l23;
}

// ---------------- causal softmax -> hi/lo bf16 P planes ----------------
__global__ __launch_bounds__(256) void softmax_causal(
    const float* __restrict__ S, __nv_bfloat16* __restrict__ Ph,
    __nv_bfloat16* __restrict__ Pl, float scale)
{
    const int t = blockIdx.x;
    const int b = blockIdx.y;
    const long ro = ((long)b * TDIM + t) * TDIM;
    const float* row = S + ro;
    const int n = t + 1;
    const int nend = ((t >> 7) + 1) << 7;
    const int tid = threadIdx.x;

    __shared__ float red[256];

    float mx = -INFINITY;
    for (int i = tid; i < n; i += 256) mx = fmaxf(mx, row[i] * scale);
    red[tid] = mx;
    __syncthreads();
    for (int s = 128; s > 0; s >>= 1) {
        if (tid < s) red[tid] = fmaxf(red[tid], red[tid + s]);
        __syncthreads();
    }
    mx = red[0];
    __syncthreads();

    float sum = 0.f;
    for (int i = tid; i < n; i += 256) sum += __expf(row[i] * scale - mx);
    red[tid] = sum;
    __syncthreads();
    for (int s = 128; s > 0; s >>= 1) {
        if (tid < s) red[tid] += red[tid + s];
        __syncthreads();
    }
    const float inv = 1.0f / red[0];

    for (int i = tid; i < n; i += 256) {
        float p = __expf(row[i] * scale - mx) * inv;
        __nv_bfloat16 hp = __float2bfloat16_rn(p);
        Ph[ro + i] = hp;
        Pl[ro + i] = __float2bfloat16_rn(p - __bfloat162float(hp));
    }
    const __nv_bfloat16 z = __float2bfloat16_rn(0.f);
    for (int i = n + tid; i < nend; i += 256) { Ph[ro + i] = z; Pl[ro + i] = z; }
}

// ---------------- transpose both V planes: vt[b][h][t] = v[b][t][h] ----------------
__global__ __launch_bounds__(256) void transpose_bth(
    const __nv_bfloat16* __restrict__ Vh, const __nv_bfloat16* __restrict__ Vl,
    __nv_bfloat16* __restrict__ VTh, __nv_bfloat16* __restrict__ VTl)
{
    __shared__ __nv_bfloat16 th[32][33], tl[32][33];
    const int b = blockIdx.z;
    const int t0 = blockIdx.x * 32;
    const int h0 = blockIdx.y * 32;
    const int tx = threadIdx.x, ty = threadIdx.y;   // 32 x 8

    const long vo = (long)b * TDIM * HDIM;

    #pragma unroll
    for (int i = 0; i < 4; i++) {
        long src = vo + (long)(t0 + ty + 8 * i) * HDIM + h0 + tx;
        th[ty + 8 * i][tx] = Vh[src];
        tl[ty + 8 * i][tx] = Vl[src];
    }
    __syncthreads();
    #pragma unroll
    for (int i = 0; i < 4; i++) {
        long dst = vo + (long)(h0 + ty + 8 * i) * TDIM + t0 + tx;
        VTh[dst] = th[tx][ty + 8 * i];
        VTl[dst] = tl[tx][ty + 8 * i];
    }
}

// ---------------- driver ----------------
extern "C" void kernel_launch(void* const* d_in, const int* in_sizes, int n_in,
                              void* d_out, int out_size)
{
    const float* x  = (const float*)d_in[0];
    const float* Wk = (const float*)d_in[1];
    const float* Wq = (const float*)d_in[2];
    const float* Wv = (const float*)d_in[3];
    float* out = (float*)d_out;

    __nv_bfloat16 *xh, *xl, *wh0, *wl0, *qh, *ql, *kh, *kl, *vh, *vl, *vth, *vtl, *ph, *pl;
    float* s;
    cudaGetSymbolAddress((void**)&xh,  g_xh);   cudaGetSymbolAddress((void**)&xl,  g_xl);
    cudaGetSymbolAddress((void**)&wh0, g_wh);   cudaGetSymbolAddress((void**)&wl0, g_wl);
    cudaGetSymbolAddress((void**)&qh,  g_qh);   cudaGetSymbolAddress((void**)&ql,  g_ql);
    cudaGetSymbolAddress((void**)&kh,  g_kh);   cudaGetSymbolAddress((void**)&kl,  g_kl);
    cudaGetSymbolAddress((void**)&vh,  g_vh);   cudaGetSymbolAddress((void**)&vl,  g_vl);
    cudaGetSymbolAddress((void**)&vth, g_vth);  cudaGetSymbolAddress((void**)&vtl, g_vtl);
    cudaGetSymbolAddress((void**)&ph,  g_ph);   cudaGetSymbolAddress((void**)&pl,  g_pl);
    cudaGetSymbolAddress((void**)&s,   g_s);

    cudaFuncSetAttribute(mma_nt, cudaFuncAttributeMaxDynamicSharedMemorySize, SMEM_BYTES);

    const int M = BDIM * TDIM;   // 8192

    // split inputs into hi/lo bf16 planes
    {
        long nx4 = NXC / 4, nw4 = NWH / 4;
        split_f32<<<(unsigned)((nx4 + 255) / 256), 256>>>(x, xh, xl, nx4);
        split_f32<<<(unsigned)((nw4 + 255) / 256), 256>>>(Wq, wh0 + 0 * NWH, wl0 + 0 * NWH, nw4);
        split_f32<<<(unsigned)((nw4 + 255) / 256), 256>>>(Wk, wh0 + 1 * NWH, wl0 + 1 * NWH, nw4);
        split_f32<<<(unsigned)((nw4 + 255) / 256), 256>>>(Wv, wh0 + 2 * NWH, wl0 + 2 * NWH, nw4);
    }

    // Projections (split outputs)
    {
        dim3 grid(HDIM / BN, M / BM, 1);
        mma_nt<<<grid, 256, SMEM_BYTES>>>(xh, xl, wh0 + 0 * NWH, wl0 + 0 * NWH,
                                          nullptr, qh, ql, CDIM, HDIM, 0, 0, 0, 0, 0, 1);
        mma_nt<<<grid, 256, SMEM_BYTES>>>(xh, xl, wh0 + 1 * NWH, wl0 + 1 * NWH,
                                          nullptr, kh, kl, CDIM, HDIM, 0, 0, 0, 0, 0, 1);
        mma_nt<<<grid, 256, SMEM_BYTES>>>(xh, xl, wh0 + 2 * NWH, wl0 + 2 * NWH,
                                          nullptr, vh, vl, CDIM, HDIM, 0, 0, 0, 0, 0, 1);
    }

    // S = Q K^T (causal tiles only), f32 out
    {
        dim3 grid(TDIM / BN, TDIM / BM, BDIM);
        mma_nt<<<grid, 256, SMEM_BYTES>>>(qh, ql, kh, kl, s, nullptr, nullptr,
                                          HDIM, TDIM, (long)TDIM * HDIM, (long)TDIM * HDIM,
                                          (long)TDIM * TDIM, 1, 0, 0);
    }

    // softmax -> P planes
    {
        dim3 grid(TDIM, BDIM);
        softmax_causal<<<grid, 256>>>(s, ph, pl, 1.0f / sqrtf((float)HDIM));
    }

    // V^T planes
    {
        dim3 grid(TDIM / 32, HDIM / 32, BDIM);
        transpose_bth<<<grid, dim3(32, 8)>>>(vh, vl, vth, vtl);
    }

    // O = P V (k clamped to diagonal), f32 out
    {
        dim3 grid(HDIM / BN, TDIM / BM, BDIM);
        mma_nt<<<grid, 256, SMEM_BYTES>>>(ph, pl, vth, vtl, out, nullptr, nullptr,
                                          TDIM, HDIM, (long)TDIM * TDIM, (long)TDIM * HDIM,
                                          (long)TDIM * HDIM, 0, 1, 0);
    }
}

// round 13
// speedup vs baseline: 5.1000x; 1.0594x over previous
#include <cuda_runtime.h>
#include <cuda_bf16.h>
#include <cstdint>
#include <math.h>

#define BDIM 4
#define TDIM 2048
#define CDIM 1024
#define HDIM 2048

#define BM 128
#define BN 128
#define BK 32
#define SPADH 40                 // bf16 per smem row (80B: 16B-aligned, LDSM conflict-free)
#define TILE_E (BM * SPADH)      // bf16 elems per tile buffer
#define TILE_B (TILE_E * 2)      // bytes per tile buffer
#define SMEM_BYTES (2 * 4 * TILE_B)   // 2 stages x 4 tiles x 10240B = 81920

// ---- global scratch planes (allocation-free rule) ----
#define NXC ((size_t)BDIM * TDIM * CDIM)
#define NWH ((size_t)HDIM * CDIM)
#define NTH ((size_t)BDIM * TDIM * HDIM)
#define NTT ((size_t)BDIM * TDIM * TDIM)
__device__ __nv_bfloat16 g_xh[NXC], g_xl[NXC];
__device__ __nv_bfloat16 g_wh[3][NWH], g_wl[3][NWH];
__device__ __nv_bfloat16 g_qh[NTH], g_ql[NTH], g_kh[NTH], g_kl[NTH];
__device__ __nv_bfloat16 g_vh[NTH], g_vl[NTH], g_vth[NTH], g_vtl[NTH];
__device__ float g_s[NTT];
__device__ __nv_bfloat16 g_ph[NTT], g_pl[NTT];

// m16n8k16 bf16 MMA (sm_80+ baseline PTX)
__device__ __forceinline__ void mma_bf16(float* c, const uint32_t* a, const uint32_t* b) {
    asm volatile(
        "mma.sync.aligned.m16n8k16.row.col.f32.bf16.bf16.f32 "
        "{%0,%1,%2,%3}, {%4,%5,%6,%7}, {%8,%9}, {%0,%1,%2,%3};"
        : "+f"(c[0]), "+f"(c[1]), "+f"(c[2]), "+f"(c[3])
        : "r"(a[0]), "r"(a[1]), "r"(a[2]), "r"(a[3]), "r"(b[0]), "r"(b[1]));
}

__device__ __forceinline__ void ldsm_x4(uint32_t* r, uint32_t addr) {
    asm volatile("ldmatrix.sync.aligned.m8n8.x4.shared.b16 {%0,%1,%2,%3}, [%4];"
                 : "=r"(r[0]), "=r"(r[1]), "=r"(r[2]), "=r"(r[3]) : "r"(addr));
}

#define CP_COMMIT() asm volatile("cp.async.commit_group;" ::: "memory")
#define CP_WAIT0()  asm volatile("cp.async.wait_group 0;" ::: "memory")
#define CP_WAIT1()  asm volatile("cp.async.wait_group 1;" ::: "memory")

// ---------------- 3xBF16 NT GEMM, cp.async double-buffered, LDSM frags ----------------
// C[m,n] = sum_k A[m*K+k]*B[n*K+k], A/B given as hi/lo bf16 planes (K-major).
// split=0: write f32 to Cf.  split=1: write hi/lo bf16 planes Ch/Cl.
__global__ __launch_bounds__(256, 2) void mma_nt(
    const __nv_bfloat16* __restrict__ Ah, const __nv_bfloat16* __restrict__ Al,
    const __nv_bfloat16* __restrict__ Bh, const __nv_bfloat16* __restrict__ Bl,
    float* __restrict__ Cf, __nv_bfloat16* __restrict__ Ch, __nv_bfloat16* __restrict__ Cl,
    int K, int ldc, long sA, long sB, long sC, int causal, int clampk, int split)
{
    const int m0 = blockIdx.y * BM;
    const int n0 = blockIdx.x * BN;
    if (causal && n0 > m0) return;

    const int b = blockIdx.z;
    Ah += (long)b * sA;  Al += (long)b * sA;
    Bh += (long)b * sB;  Bl += (long)b * sB;

    extern __shared__ __nv_bfloat16 sm[];
    const uint32_t smb = (uint32_t)__cvta_generic_to_shared(sm);

    const int tid  = threadIdx.x;
    const int wid  = tid >> 5;
    const int lane = tid & 31;
    const int g  = lane >> 2;
    const int tg = lane & 3;
    const int wm = (wid >> 2) * 64;
    const int wn = (wid & 3) * 32;

    // LDSM per-thread source addresses (bytes)
    // A x4: matrices {r0..7,k0..7},{r8..15,k0..7},{r0..7,k8..15},{r8..15,k8..15}
    const uint32_t a_base = smb + (uint32_t)(((wm + (lane & 15)) * SPADH + ((lane >> 4) << 3)) * 2);
    // B x4 (two nt per load): {n0..7,k0..7},{n0..7,k8..15},{n8..15,k0..7},{n8..15,k8..15}
    const uint32_t b_base = smb + (uint32_t)(((wn + ((lane >> 4) << 3) + (lane & 7)) * SPADH
                                              + (((lane >> 3) & 1) << 3)) * 2);

    const int kEnd = clampk ? (m0 + BM) : K;
    const int nstages = kEnd / BK;

    // cp.async chunk coords (2 chunks of 16B per tile per thread)
    const int r0c = tid >> 2,          c0c = tid & 3;
    const int r1c = (tid + 256) >> 2,  c1c = (tid + 256) & 3;

    const __nv_bfloat16* planes[4] = {Ah, Al, Bh, Bl};
    const int rbase[4] = {m0, m0, n0, n0};

    auto load_stage = [&](int buf, int k0) {
        #pragma unroll
        for (int p = 0; p < 4; p++) {
            __nv_bfloat16* tb = sm + (buf * 4 + p) * TILE_E;
            {
                uint32_t dst = (uint32_t)__cvta_generic_to_shared(tb + r0c * SPADH + c0c * 8);
                const void* src = planes[p] + (long)(rbase[p] + r0c) * K + k0 + c0c * 8;
                asm volatile("cp.async.cg.shared.global [%0], [%1], 16;" :: "r"(dst), "l"(src));
            }
            {
                uint32_t dst = (uint32_t)__cvta_generic_to_shared(tb + r1c * SPADH + c1c * 8);
                const void* src = planes[p] + (long)(rbase[p] + r1c) * K + k0 + c1c * 8;
                asm volatile("cp.async.cg.shared.global [%0], [%1], 16;" :: "r"(dst), "l"(src));
            }
        }
        CP_COMMIT();
    };

    float acc[4][4][4] = {};

    load_stage(0, 0);

    for (int s = 0; s < nstages; s++) {
        if (s + 1 < nstages) { load_stage((s + 1) & 1, (s + 1) * BK); CP_WAIT1(); }
        else                 { CP_WAIT0(); }
        __syncthreads();

        const uint32_t tAh = (uint32_t)(((s & 1) * 4 + 0) * TILE_B);
        const uint32_t tAl = (uint32_t)(((s & 1) * 4 + 1) * TILE_B);
        const uint32_t tBh = (uint32_t)(((s & 1) * 4 + 2) * TILE_B);
        const uint32_t tBl = (uint32_t)(((s & 1) * 4 + 3) * TILE_B);

        #pragma unroll
        for (int ks = 0; ks < BK; ks += 16) {
            const uint32_t ksb = (uint32_t)(ks * 2);
            uint32_t af[4][4], bh[2][4];

            // Phase 1: ah * bh
            #pragma unroll
            for (int mt = 0; mt < 4; mt++)
                ldsm_x4(af[mt], a_base + tAh + (uint32_t)(mt * 16 * SPADH * 2) + ksb);
            #pragma unroll
            for (int p = 0; p < 2; p++)
                ldsm_x4(bh[p], b_base + tBh + (uint32_t)(p * 16 * SPADH * 2) + ksb);
            #pragma unroll
            for (int mt = 0; mt < 4; mt++)
                #pragma unroll
                for (int nt = 0; nt < 4; nt++)
                    mma_bf16(acc[mt][nt], af[mt], &bh[nt >> 1][(nt & 1) * 2]);

            // Phase 2: ah * bl
            uint32_t bl[2][4];
            #pragma unroll
            for (int p = 0; p < 2; p++)
                ldsm_x4(bl[p], b_base + tBl + (uint32_t)(p * 16 * SPADH * 2) + ksb);
            #pragma unroll
            for (int mt = 0; mt < 4; mt++)
                #pragma unroll
                for (int nt = 0; nt < 4; nt++)
                    mma_bf16(acc[mt][nt], af[mt], &bl[nt >> 1][(nt & 1) * 2]);

            // Phase 3: al * bh (reuse af regs for Al)
            #pragma unroll
            for (int mt = 0; mt < 4; mt++)
                ldsm_x4(af[mt], a_base + tAl + (uint32_t)(mt * 16 * SPADH * 2) + ksb);
            #pragma unroll
            for (int mt = 0; mt < 4; mt++)
                #pragma unroll
                for (int nt = 0; nt < 4; nt++)
                    mma_bf16(acc[mt][nt], af[mt], &bh[nt >> 1][(nt & 1) * 2]);
        }
        __syncthreads();
    }

    // ---- epilogue ----
    if (split) {
        Ch += (long)blockIdx.z * sC;  Cl += (long)blockIdx.z * sC;
        #pragma unroll
        for (int mt = 0; mt < 4; mt++) {
            #pragma unroll
            for (int nt = 0; nt < 4; nt++) {
                const int row = m0 + wm + mt * 16 + g;
                const int col = n0 + wn + nt * 8 + tg * 2;
                #pragma unroll
                for (int h = 0; h < 2; h++) {
                    float2 v = {acc[mt][nt][2 * h], acc[mt][nt][2 * h + 1]};
                    __nv_bfloat162 hp = __float22bfloat162_rn(v);
                    __nv_bfloat162 lp = __float22bfloat162_rn(make_float2(
                        v.x - __bfloat162float(hp.x), v.y - __bfloat162float(hp.y)));
                    long off = (long)(row + 8 * h) * ldc + col;
                    *(__nv_bfloat162*)&Ch[off] = hp;
                    *(__nv_bfloat162*)&Cl[off] = lp;
                }
            }
        }
    } else {
        Cf += (long)blockIdx.z * sC;
        #pragma unroll
        for (int mt = 0; mt < 4; mt++) {
            #pragma unroll
            for (int nt = 0; nt < 4; nt++) {
                const int row = m0 + wm + mt * 16 + g;
                const int col = n0 + wn + nt * 8 + tg * 2;
                float2 lo = {acc[mt][nt][0], acc[mt][nt][1]};
                float2 hi = {acc[mt][nt][2], acc[mt][nt][3]};
                *(float2*)&Cf[(long)row * ldc + col] = lo;
                *(float2*)&Cf[(long)(row + 8) * ldc + col] = hi;
            }
        }
    }
}

// ---------------- f32 -> hi/lo bf16 planes ----------------
__global__ __launch_bounds__(256) void split_f32(
    const float* __restrict__ src, __nv_bfloat16* __restrict__ h,
    __nv_bfloat16* __restrict__ l, long n4)
{
    long i = ((long)blockIdx.x * 256 + threadIdx.x);
    if (i >= n4) return;
    float4 v = *(const float4*)(src + i * 4);
    __nv_bfloat162 h01 = __float22bfloat162_rn(make_float2(v.x, v.y));
    __nv_bfloat162 h23 = __float22bfloat162_rn(make_float2(v.z, v.w));
    __nv_bfloat162 l01 = __float22bfloat162_rn(make_float2(
        v.x - __bfloat162float(h01.x), v.y - __bfloat162float(h01.y)));
    __nv_bfloat162 l23 = __float22bfloat162_rn(make_float2(
        v.z - __bfloat162float(h23.x), v.w - __bfloat162float(h23.y)));
    *(__nv_bfloat162*)&h[i * 4]     = h01;
    *(__nv_bfloat162*)&h[i * 4 + 2] = h23;
    *(__nv_bfloat162*)&l[i * 4]     = l01;
    *(__nv_bfloat162*)&l[i * 4 + 2] = l23;
}

// ---------------- causal softmax -> hi/lo bf16 P planes ----------------
__global__ __launch_bounds__(256) void softmax_causal(
    const float* __restrict__ S, __nv_bfloat16* __restrict__ Ph,
    __nv_bfloat16* __restrict__ Pl, float scale)
{
    const int t = blockIdx.x;
    const int b = blockIdx.y;
    const long ro = ((long)b * TDIM + t) * TDIM;
    const float* row = S + ro;
    const int n = t + 1;
    const int nend = ((t >> 7) + 1) << 7;
    const int tid = threadIdx.x;

    __shared__ float red[256];

    float mx = -INFINITY;
    for (int i = tid; i < n; i += 256) mx = fmaxf(mx, row[i] * scale);
    red[tid] = mx;
    __syncthreads();
    for (int s = 128; s > 0; s >>= 1) {
        if (tid < s) red[tid] = fmaxf(red[tid], red[tid + s]);
        __syncthreads();
    }
    mx = red[0];
    __syncthreads();

    float sum = 0.f;
    for (int i = tid; i < n; i += 256) sum += __expf(row[i] * scale - mx);
    red[tid] = sum;
    __syncthreads();
    for (int s = 128; s > 0; s >>= 1) {
        if (tid < s) red[tid] += red[tid + s];
        __syncthreads();
    }
    const float inv = 1.0f / red[0];

    for (int i = tid; i < n; i += 256) {
        float p = __expf(row[i] * scale - mx) * inv;
        __nv_bfloat16 hp = __float2bfloat16_rn(p);
        Ph[ro + i] = hp;
        Pl[ro + i] = __float2bfloat16_rn(p - __bfloat162float(hp));
    }
    const __nv_bfloat16 z = __float2bfloat16_rn(0.f);
    for (int i = n + tid; i < nend; i += 256) { Ph[ro + i] = z; Pl[ro + i] = z; }
}

// ---------------- transpose both V planes: vt[b][h][t] = v[b][t][h] ----------------
__global__ __launch_bounds__(256) void transpose_bth(
    const __nv_bfloat16* __restrict__ Vh, const __nv_bfloat16* __restrict__ Vl,
    __nv_bfloat16* __restrict__ VTh, __nv_bfloat16* __restrict__ VTl)
{
    __shared__ __nv_bfloat16 th[32][33], tl[32][33];
    const int b = blockIdx.z;
    const int t0 = blockIdx.x * 32;
    const int h0 = blockIdx.y * 32;
    const int tx = threadIdx.x, ty = threadIdx.y;   // 32 x 8

    const long vo = (long)b * TDIM * HDIM;

    #pragma unroll
    for (int i = 0; i < 4; i++) {
        long src = vo + (long)(t0 + ty + 8 * i) * HDIM + h0 + tx;
        th[ty + 8 * i][tx] = Vh[src];
        tl[ty + 8 * i][tx] = Vl[src];
    }
    __syncthreads();
    #pragma unroll
    for (int i = 0; i < 4; i++) {
        long dst = vo + (long)(h0 + ty + 8 * i) * TDIM + t0 + tx;
        VTh[dst] = th[tx][ty + 8 * i];
        VTl[dst] = tl[tx][ty + 8 * i];
    }
}

// ---------------- driver ----------------
extern "C" void kernel_launch(void* const* d_in, const int* in_sizes, int n_in,
                              void* d_out, int out_size)
{
    const float* x  = (const float*)d_in[0];
    const float* Wk = (const float*)d_in[1];
    const float* Wq = (const float*)d_in[2];
    const float* Wv = (const float*)d_in[3];
    float* out = (float*)d_out;

    __nv_bfloat16 *xh, *xl, *wh0, *wl0, *qh, *ql, *kh, *kl, *vh, *vl, *vth, *vtl, *ph, *pl;
    float* s;
    cudaGetSymbolAddress((void**)&xh,  g_xh);   cudaGetSymbolAddress((void**)&xl,  g_xl);
    cudaGetSymbolAddress((void**)&wh0, g_wh);   cudaGetSymbolAddress((void**)&wl0, g_wl);
    cudaGetSymbolAddress((void**)&qh,  g_qh);   cudaGetSymbolAddress((void**)&ql,  g_ql);
    cudaGetSymbolAddress((void**)&kh,  g_kh);   cudaGetSymbolAddress((void**)&kl,  g_kl);
    cudaGetSymbolAddress((void**)&vh,  g_vh);   cudaGetSymbolAddress((void**)&vl,  g_vl);
    cudaGetSymbolAddress((void**)&vth, g_vth);  cudaGetSymbolAddress((void**)&vtl, g_vtl);
    cudaGetSymbolAddress((void**)&ph,  g_ph);   cudaGetSymbolAddress((void**)&pl,  g_pl);
    cudaGetSymbolAddress((void**)&s,   g_s);

    cudaFuncSetAttribute(mma_nt, cudaFuncAttributeMaxDynamicSharedMemorySize, SMEM_BYTES);

    const int M = BDIM * TDIM;   // 8192

    // split inputs into hi/lo bf16 planes
    {
        long nx4 = NXC / 4, nw4 = NWH / 4;
        split_f32<<<(unsigned)((nx4 + 255) / 256), 256>>>(x, xh, xl, nx4);
        split_f32<<<(unsigned)((nw4 + 255) / 256), 256>>>(Wq, wh0 + 0 * NWH, wl0 + 0 * NWH, nw4);
        split_f32<<<(unsigned)((nw4 + 255) / 256), 256>>>(Wk, wh0 + 1 * NWH, wl0 + 1 * NWH, nw4);
        split_f32<<<(unsigned)((nw4 + 255) / 256), 256>>>(Wv, wh0 + 2 * NWH, wl0 + 2 * NWH, nw4);
    }

    // Projections (split outputs)
    {
        dim3 grid(HDIM / BN, M / BM, 1);
        mma_nt<<<grid, 256, SMEM_BYTES>>>(xh, xl, wh0 + 0 * NWH, wl0 + 0 * NWH,
                                          nullptr, qh, ql, CDIM, HDIM, 0, 0, 0, 0, 0, 1);
        mma_nt<<<grid, 256, SMEM_BYTES>>>(xh, xl, wh0 + 1 * NWH, wl0 + 1 * NWH,
                                          nullptr, kh, kl, CDIM, HDIM, 0, 0, 0, 0, 0, 1);
        mma_nt<<<grid, 256, SMEM_BYTES>>>(xh, xl, wh0 + 2 * NWH, wl0 + 2 * NWH,
                                          nullptr, vh, vl, CDIM, HDIM, 0, 0, 0, 0, 0, 1);
    }

    // S = Q K^T (causal tiles only), f32 out
    {
        dim3 grid(TDIM / BN, TDIM / BM, BDIM);
        mma_nt<<<grid, 256, SMEM_BYTES>>>(qh, ql, kh, kl, s, nullptr, nullptr,
                                          HDIM, TDIM, (long)TDIM * HDIM, (long)TDIM * HDIM,
                                          (long)TDIM * TDIM, 1, 0, 0);
    }

    // softmax -> P planes
    {
        dim3 grid(TDIM, BDIM);
        softmax_causal<<<grid, 256>>>(s, ph, pl, 1.0f / sqrtf((float)HDIM));
    }

    // V^T planes
    {
        dim3 grid(TDIM / 32, HDIM / 32, BDIM);
        transpose_bth<<<grid, dim3(32, 8)>>>(vh, vl, vth, vtl);
    }

    // O = P V (k clamped to diagonal), f32 out
    {
        dim3 grid(HDIM / BN, TDIM / BM, BDIM);
        mma_nt<<<grid, 256, SMEM_BYTES>>>(ph, pl, vth, vtl, out, nullptr, nullptr,
                                          TDIM, HDIM, (long)TDIM * TDIM, (long)TDIM * HDIM,
                                          (long)TDIM * HDIM, 0, 1, 0);
    }
}